// round 13
// baseline (speedup 1.0000x reference)
#include <cuda_runtime.h>
#include <cstdint>

// Problem constants
#define B_SZ   1024
#define F_SZ   784
#define OUT_F  1024
#define OR_T   32
#define AND_T  16
#define NROWS  785               // positive literals: idx 0 (const-true) + x[0..783]
#define NBG    32                // batch-groups (full batch range per CTA)

// Single-polarity, full-batch table: g_P[idx][bg], row = 128 B.
#define TBL_WORDS (NROWS * NBG)              // 25120 words = 100480 B
#define TBL_BYTES (TBL_WORDS * 4)
__device__ __align__(16) uint32_t g_P[TBL_WORDS];

// ---------------------------------------------------------------------------
// Pack kernel: grid (25, 32), 128 threads. Coalesced 32x32 tile load ->
// smem transpose -> ballot -> positive-mask table write.
// ---------------------------------------------------------------------------
__global__ __launch_bounds__(128) void pack_kernel(const float* __restrict__ x) {
    __shared__ float tile[32][33];

    const int ft  = blockIdx.x;
    const int bg  = blockIdx.y;               // 0..31
    const int tid = threadIdx.x;
    const int f0  = ft * 32;

    const int c  = tid & 31;
    const int r0 = tid >> 5;
    #pragma unroll
    for (int r = r0; r < 32; r += 4) {
        const int f = f0 + c;
        tile[r][c] = (f < F_SZ) ? x[(size_t)(bg * 32 + r) * F_SZ + f] : 0.0f;
    }
    __syncthreads();

    const int lane = tid & 31;
    const int w    = tid >> 5;
    #pragma unroll
    for (int ff = w; ff < 32; ff += 4) {
        const int f = f0 + ff;
        if (f >= F_SZ) break;
        uint32_t m = __ballot_sync(0xFFFFFFFFu, tile[lane][ff] != 0.0f);
        if (lane == 0) g_P[(size_t)(1 + f) * NBG + bg] = m;
    }
    if (ft == 0 && tid == 0) g_P[bg] = 0xFFFFFFFFu;   // const-true row
}

// ---------------------------------------------------------------------------
// Logic kernel: 256 blocks x 512 threads, 2 CTAs/SM (110.7KB smem each).
//  - 100KB positive-mask table via TMA bulk copy (4 x 25120B chunks).
//  - Negated literals inline: eff = idx - (neg & 784); acc &= (row ^ negmask)
//    (one LOP3 for the apply).
//  - Warp quad per output (q = wid&3 handles 8 OR-terms); lane = batch-group
//    -> scalar LDS gathers are conflict-free (32 consecutive words).
// ---------------------------------------------------------------------------
#define OPB 4
#define NTHREADS 512
#define W_WORDS (OPB * OR_T * AND_T)                  // 2048 words = 8 KB
#define RES_WORDS (OPB * 4 * NBG)                     // 512 words
#define MBAR_OFF_W (TBL_WORDS + W_WORDS + RES_WORDS)  // 27680 (16B aligned)
#define SMEM_BYTES ((MBAR_OFF_W + 4) * 4)             // 110736 B
#define N_CHUNKS    4
#define CHUNK_BYTES (TBL_BYTES / N_CHUNKS)            // 25120 = 16 * 1570

__global__ __launch_bounds__(NTHREADS, 2) void logic_kernel(
    const int* __restrict__ weights, float* __restrict__ out) {

    extern __shared__ uint32_t smem[];
    uint32_t* sP   = smem;                      // table (25120 words)
    uint32_t* sw   = smem + TBL_WORDS;          // weights (2048 words)
    uint32_t* resb = sw + W_WORDS;              // results [o][q][bg]
    uint32_t  mbar_addr;
    {
        uint64_t* mb64 = (uint64_t*)(smem + MBAR_OFF_W);
        asm("{ .reg .u64 t; cvta.to.shared.u64 t, %1; cvt.u32.u64 %0, t; }"
            : "=r"(mbar_addr) : "l"((void*)mb64));
    }

    const int tid   = threadIdx.x;
    const int oBase = blockIdx.x * OPB;

    if (tid == 0) {
        asm volatile("mbarrier.init.shared.b64 [%0], 1;" :: "r"(mbar_addr) : "memory");
    }
    __syncthreads();

    if (tid == 0) {
        asm volatile("mbarrier.arrive.expect_tx.shared.b64 _, [%0], %1;"
                     :: "r"(mbar_addr), "r"((uint32_t)TBL_BYTES) : "memory");
        const char* gsrc = (const char*)g_P;
        uint32_t sdst;
        asm("{ .reg .u64 t; cvta.to.shared.u64 t, %1; cvt.u32.u64 %0, t; }"
            : "=r"(sdst) : "l"((void*)sP));
        #pragma unroll
        for (int i = 0; i < N_CHUNKS; ++i) {
            asm volatile(
                "cp.async.bulk.shared::cta.global.mbarrier::complete_tx::bytes "
                "[%0], [%1], %2, [%3];"
                :: "r"(sdst + i * CHUNK_BYTES), "l"(gsrc + (size_t)i * CHUNK_BYTES),
                   "r"((uint32_t)CHUNK_BYTES), "r"(mbar_addr) : "memory");
        }
    }

    // Stage weights while DMA runs (1 uint4 per thread, coalesced)
    {
        const uint4* wsrc = (const uint4*)(weights + (size_t)oBase * OR_T * AND_T);
        ((uint4*)sw)[tid] = wsrc[tid];
    }
    __syncthreads();

    // Wait for the table
    {
        uint32_t done;
        asm volatile(
            "{\n\t.reg .pred p;\n\t"
            "mbarrier.try_wait.parity.acquire.cta.shared::cta.b64 p, [%1], 0;\n\t"
            "selp.b32 %0, 1, 0, p;\n\t}"
            : "=r"(done) : "r"(mbar_addr) : "memory");
        if (!done) {
            asm volatile(
                "{\n\t.reg .pred P1;\n\t"
                "WL_%=:\n\t"
                "mbarrier.try_wait.parity.acquire.cta.shared::cta.b64 P1, [%0], 0, 0x989680;\n\t"
                "@P1 bra.uni WD_%=;\n\t"
                "bra.uni WL_%=;\n\t"
                "WD_%=:\n\t}"
                :: "r"(mbar_addr) : "memory");
        }
    }

    const int wid  = tid >> 5;                  // 0..15
    const int lane = tid & 31;                  // batch-group (conflict-free)
    const int o    = wid >> 2;                  // output within block (0..3)
    const int q    = wid & 3;                   // term quarter (8 terms)

    const uint32_t* swb = sw + o * (OR_T * AND_T) + q * (8 * AND_T);

    // Gather with inline negation: idx>784 -> positive row (idx-784), XOR ~0.
    // The XOR+AND folds into a single LOP3.
    #define GV(i, acc) do {                                                   \
        const uint32_t _i  = (i);                                             \
        const uint32_t _xm = (_i > 784u) ? 0xFFFFFFFFu : 0u;                  \
        const uint32_t _e  = (_i > 784u) ? (_i - 784u) : _i;                  \
        (acc) &= (sP[_e * NBG + lane] ^ _xm);                                 \
    } while (0)

    uint32_t res = 0;
    #pragma unroll
    for (int t = 0; t < 8; ++t) {
        const uint4* tw4 = (const uint4*)(swb + t * AND_T);
        uint32_t m0 = ~0u, m1 = ~0u;
        uint32_t orw = 0;
        #pragma unroll
        for (int k4 = 0; k4 < 4; ++k4) {
            const uint4 w4 = tw4[k4];           // uniform LDS.128 broadcast
            orw |= (w4.x | w4.y | w4.z | w4.w);
            GV(w4.x, m0);
            GV(w4.y, m1);
            GV(w4.z, m0);
            GV(w4.w, m1);
        }
        if (orw != 0) res |= (m0 & m1);
    }
    #undef GV

    resb[(o * 4 + q) * NBG + lane] = res;
    __syncthreads();

    // Store: per batch, 4 contiguous floats (one float4), OR over the 4 quads
    #pragma unroll
    for (int b = tid; b < B_SZ; b += NTHREADS) {       // 2 iterations
        const int bg = b >> 5;
        const int j  = b & 31;
        float4 v;
        #define GETBIT(ow) ((((resb[((ow)*4+0)*NBG + bg] | resb[((ow)*4+1)*NBG + bg] | \
                               resb[((ow)*4+2)*NBG + bg] | resb[((ow)*4+3)*NBG + bg]) >> j) & 1u))
        v.x = (float)GETBIT(0); v.y = (float)GETBIT(1);
        v.z = (float)GETBIT(2); v.w = (float)GETBIT(3);
        #undef GETBIT
        *(float4*)(out + (size_t)b * OUT_F + oBase) = v;
    }
}

// ---------------------------------------------------------------------------
extern "C" void kernel_launch(void* const* d_in, const int* in_sizes, int n_in,
                              void* d_out, int out_size) {
    const float* x       = (const float*)d_in[0];   // (1024, 784) float32
    const int*   weights = (const int*)d_in[1];     // (1024, 32, 16) int32
    float*       out     = (float*)d_out;           // (1024, 1024) float32

    cudaFuncSetAttribute(logic_kernel,
                         cudaFuncAttributeMaxDynamicSharedMemorySize, SMEM_BYTES);

    dim3 pgrid(25, 32);
    pack_kernel<<<pgrid, 128>>>(x);
    logic_kernel<<<OUT_F / OPB, NTHREADS, SMEM_BYTES>>>(weights, out);
}

// round 14
// speedup vs baseline: 1.3175x; 1.3175x over previous
#include <cuda_runtime.h>
#include <cstdint>

// Problem constants
#define B_SZ   1024
#define F_SZ   784
#define OUT_F  1024
#define OR_T   32
#define AND_T  16
#define NLIT   (1 + 2 * F_SZ)   // 1569 literals
#define NBG    (B_SZ / 32)      // 32 words per literal row = 128 B
#define TBL_WORDS (NLIT * NBG)  // 50208 words = 200832 B
#define TBL_BYTES (TBL_WORDS * 4)

#define OUTS_PER_BLOCK 8
#define NTHREADS 512
#define CLUSTER_SZ 4
#define W_WORDS (OUTS_PER_BLOCK * OR_T * AND_T)     // 4096 words = 16384 B
#define W_BYTES (W_WORDS * 4)
#define RES_WORDS (OUTS_PER_BLOCK * 2 * NBG)        // 512 words
#define MBAR_OFF_W (TBL_WORDS + W_WORDS + RES_WORDS + 4)
#define SMEM_BYTES ((MBAR_OFF_W + 4) * 4)           // ~219.3 KB

__device__ __align__(16) uint32_t g_T[TBL_WORDS];

// ---------------------------------------------------------------------------
// Pack kernel: grid (25, 32), 128 threads (~1us). Dual-polarity table.
// ---------------------------------------------------------------------------
__global__ __launch_bounds__(128) void pack_kernel(const float* __restrict__ x) {
    __shared__ float tile[32][33];

    const int ft  = blockIdx.x;
    const int bg  = blockIdx.y;
    const int tid = threadIdx.x;
    const int f0  = ft * 32;

    const int c  = tid & 31;
    const int r0 = tid >> 5;
    #pragma unroll
    for (int r = r0; r < 32; r += 4) {
        const int f = f0 + c;
        tile[r][c] = (f < F_SZ) ? x[(size_t)(bg * 32 + r) * F_SZ + f] : 0.0f;
    }
    __syncthreads();

    const int lane = tid & 31;
    const int w    = tid >> 5;
    #pragma unroll
    for (int ff = w; ff < 32; ff += 4) {
        const int f = f0 + ff;
        if (f >= F_SZ) break;
        uint32_t m = __ballot_sync(0xFFFFFFFFu, tile[lane][ff] != 0.0f);
        if (lane == 0) {
            g_T[(size_t)(1 + f) * NBG + bg]        = m;
            g_T[(size_t)(1 + F_SZ + f) * NBG + bg] = ~m;
        }
    }
    if (ft == 0 && tid == 0) g_T[bg] = 0xFFFFFFFFu;
}

// ---------------------------------------------------------------------------
// Logic kernel: 128 blocks (clusters of 4) x 512 threads.
//  - Cluster leader multicasts the 200KB table to all 4 CTAs' smem (8 bulk
//    chunks, mask 0xF): chip L2 fill traffic drops 4x vs per-CTA copies.
//  - Each CTA bulk-copies its own 16KB weights on the same mbarrier
//    (expect_tx = table + weights).
//  - Gather identical to the best-known R9 form: warp pair per output, lane =
//    (term-of-pair, bg-pair), conflict-free LDS.64, no per-gather ALU.
// ---------------------------------------------------------------------------
__global__ __launch_bounds__(NTHREADS, 1) __cluster_dims__(CLUSTER_SZ, 1, 1)
void logic_kernel(const int* __restrict__ weights, float* __restrict__ out) {

    extern __shared__ uint32_t smem[];
    uint32_t* sT   = smem;                     // table (50208 words)
    uint32_t* sw   = smem + TBL_WORDS;         // weights (4096 words)
    uint32_t* resb = sw + W_WORDS;             // results (512 words)
    uint32_t  mbar_addr;
    {
        uint64_t* mb64 = (uint64_t*)(smem + MBAR_OFF_W);
        asm("{ .reg .u64 t; cvta.to.shared.u64 t, %1; cvt.u32.u64 %0, t; }"
            : "=r"(mbar_addr) : "l"((void*)mb64));
    }

    const int tid   = threadIdx.x;
    const int oBase = blockIdx.x * OUTS_PER_BLOCK;
    uint32_t rank;
    asm("mov.u32 %0, %%cluster_ctarank;" : "=r"(rank));

    if (tid == 0) {
        asm volatile("mbarrier.init.shared.b64 [%0], 1;" :: "r"(mbar_addr) : "memory");
    }
    __syncthreads();
    if (tid == 0) {
        asm volatile("mbarrier.arrive.expect_tx.shared.b64 _, [%0], %1;"
                     :: "r"(mbar_addr),
                        "r"((uint32_t)(TBL_BYTES + W_BYTES)) : "memory");
    }
    // All cluster mbarriers initialized + expecting before any multicast lands
    asm volatile("barrier.cluster.arrive.aligned;" ::: "memory");
    asm volatile("barrier.cluster.wait.aligned;"   ::: "memory");

    if (tid == 0) {
        uint32_t sdst;
        asm("{ .reg .u64 t; cvta.to.shared.u64 t, %1; cvt.u32.u64 %0, t; }"
            : "=r"(sdst) : "l"((void*)sT));

        if (rank == 0) {
            // Leader: multicast the table to all 4 CTAs (8 x 25104B chunks)
            const char* gsrc = (const char*)g_T;
            const uint32_t chunk = TBL_BYTES / 8;      // 25104 = 16*1569
            #pragma unroll
            for (int i = 0; i < 8; ++i) {
                asm volatile(
                    "cp.async.bulk.shared::cluster.global.mbarrier::complete_tx::bytes"
                    ".multicast::cluster [%0], [%1], %2, [%3], %4;"
                    :: "r"(sdst + i * chunk), "l"(gsrc + (size_t)i * chunk),
                       "r"(chunk), "r"(mbar_addr),
                       "h"((uint16_t)((1u << CLUSTER_SZ) - 1u)) : "memory");
            }
        }
        // Every CTA: its own weights (16384B, non-multicast)
        {
            const char* wsrc = (const char*)(weights + (size_t)oBase * OR_T * AND_T);
            asm volatile(
                "cp.async.bulk.shared::cta.global.mbarrier::complete_tx::bytes "
                "[%0], [%1], %2, [%3];"
                :: "r"(sdst + (uint32_t)TBL_BYTES), "l"(wsrc),
                   "r"((uint32_t)W_BYTES), "r"(mbar_addr) : "memory");
        }
    }
    __syncthreads();

    // Wait for table + weights
    {
        uint32_t done;
        asm volatile(
            "{\n\t.reg .pred p;\n\t"
            "mbarrier.try_wait.parity.acquire.cta.shared::cta.b64 p, [%1], 0;\n\t"
            "selp.b32 %0, 1, 0, p;\n\t}"
            : "=r"(done) : "r"(mbar_addr) : "memory");
        if (!done) {
            asm volatile(
                "{\n\t.reg .pred P1;\n\t"
                "WL_%=:\n\t"
                "mbarrier.try_wait.parity.acquire.cta.shared::cta.b64 P1, [%0], 0, 0x989680;\n\t"
                "@P1 bra.uni WD_%=;\n\t"
                "bra.uni WL_%=;\n\t"
                "WD_%=:\n\t}"
                :: "r"(mbar_addr) : "memory");
        }
    }

    const int wid  = tid >> 5;                 // 0..15
    const int lane = tid & 31;
    const int o    = wid >> 1;                 // output within block (0..7)
    const int h    = wid & 1;                  // term half (0..1)
    const int th   = lane >> 4;                // term selector within pass
    const int bgp  = lane & 15;                // batch-group pair (uint2)

    const uint32_t* swb = sw + o * (OR_T * AND_T);
    const uint2*    sT2 = (const uint2*)sT;

    uint2 res = make_uint2(0u, 0u);
    #pragma unroll
    for (int t2 = 0; t2 < 8; ++t2) {
        const int t = h * 16 + t2 * 2 + th;             // this lane's term
        const uint4* tw4 = (const uint4*)(swb + t * AND_T);
        uint2 m0 = make_uint2(~0u, ~0u), m1 = make_uint2(~0u, ~0u);
        uint32_t orw = 0;
        #pragma unroll
        for (int k4 = 0; k4 < 4; ++k4) {
            const uint4 w4 = tw4[k4];                   // broadcast LDS.128
            orw |= (w4.x | w4.y | w4.z | w4.w);
            const uint2 a = sT2[w4.x * 16 + bgp];       // LDS.64 gathers
            const uint2 b = sT2[w4.y * 16 + bgp];
            const uint2 c = sT2[w4.z * 16 + bgp];
            const uint2 d = sT2[w4.w * 16 + bgp];
            m0.x &= a.x & c.x;  m0.y &= a.y & c.y;
            m1.x &= b.x & d.x;  m1.y &= b.y & d.y;
        }
        const uint32_t sel = (orw != 0) ? ~0u : 0u;     // all-zero term masked
        res.x |= m0.x & m1.x & sel;
        res.y |= m0.y & m1.y & sel;
    }
    // OR across th (lanes l <-> l+16 share bgp)
    res.x |= __shfl_xor_sync(0xFFFFFFFFu, res.x, 16);
    res.y |= __shfl_xor_sync(0xFFFFFFFFu, res.y, 16);

    if (lane < 16) {
        resb[(o * 2 + h) * NBG + bgp * 2]     = res.x;  // bg even
        resb[(o * 2 + h) * NBG + bgp * 2 + 1] = res.y;  // bg odd
    }
    __syncthreads();

    // Store: per batch, 8 contiguous floats (two float4), OR over term halves
    #pragma unroll
    for (int b = tid; b < B_SZ; b += NTHREADS) {        // 2 iterations
        const int bg = b >> 5;
        const int j  = b & 31;
        float4 v0, v1;
        #define GETBIT(ow) ((((resb[((ow)*2+0)*NBG + bg] | \
                               resb[((ow)*2+1)*NBG + bg]) >> j) & 1u))
        v0.x = (float)GETBIT(0); v0.y = (float)GETBIT(1);
        v0.z = (float)GETBIT(2); v0.w = (float)GETBIT(3);
        v1.x = (float)GETBIT(4); v1.y = (float)GETBIT(5);
        v1.z = (float)GETBIT(6); v1.w = (float)GETBIT(7);
        #undef GETBIT
        float4* dst = (float4*)(out + (size_t)b * OUT_F + oBase);
        dst[0] = v0;
        dst[1] = v1;
    }
}

// ---------------------------------------------------------------------------
extern "C" void kernel_launch(void* const* d_in, const int* in_sizes, int n_in,
                              void* d_out, int out_size) {
    const float* x       = (const float*)d_in[0];   // (1024, 784) float32
    const int*   weights = (const int*)d_in[1];     // (1024, 32, 16) int32
    float*       out     = (float*)d_out;           // (1024, 1024) float32

    cudaFuncSetAttribute(logic_kernel,
                         cudaFuncAttributeMaxDynamicSharedMemorySize, SMEM_BYTES);

    dim3 pgrid(25, 32);
    pack_kernel<<<pgrid, 128>>>(x);
    logic_kernel<<<OUT_F / OUTS_PER_BLOCK, NTHREADS, SMEM_BYTES>>>(weights, out);
}